// round 15
// baseline (speedup 1.0000x reference)
#include <cuda_runtime.h>
#include <cuda_fp16.h>
#include <cstdint>

// Problem constants
#define B_SZ   4
#define C_IN   512
#define HW     4096
#define HH     64
#define WW     64
#define NCH3   1536
#define GROUPS 192
#define NHEAD  128
#define EPSF   1e-15f

// ---------------- scratch ----------------
__device__ float  g_qkv[(long)B_SZ * NCH3 * HW];
__device__ float  g_agg[(long)B_SZ * NCH3 * HW];
__device__ float  g_vk [B_SZ * NHEAD * 72];
__device__ __half g_xt1[(long)B_SZ * HW * 512];    // x transposed  [b][n][k]
__device__ __half g_xt2[(long)B_SZ * HW * 1024];   // outn          [b][n][k]
__device__ __half g_wh1[NCH3 * 512];               // w_qkv fp16
__device__ __half g_wh2[512 * 1024];               // w_proj fp16

// ---------------- helpers ----------------
__device__ __forceinline__ void mma_f16(float (&c)[4], const uint32_t (&a)[4], const uint32_t (&b)[2]) {
    asm volatile(
        "mma.sync.aligned.m16n8k16.row.col.f32.f16.f16.f32 "
        "{%0,%1,%2,%3}, {%4,%5,%6,%7}, {%8,%9}, {%0,%1,%2,%3};\n"
        : "+f"(c[0]), "+f"(c[1]), "+f"(c[2]), "+f"(c[3])
        : "r"(a[0]), "r"(a[1]), "r"(a[2]), "r"(a[3]), "r"(b[0]), "r"(b[1]));
}
__device__ __forceinline__ void ldmx4(uint32_t& r0, uint32_t& r1, uint32_t& r2, uint32_t& r3,
                                      uint32_t addr) {
    asm volatile("ldmatrix.sync.aligned.m8n8.x4.shared.b16 {%0,%1,%2,%3}, [%4];"
        : "=r"(r0), "=r"(r1), "=r"(r2), "=r"(r3) : "r"(addr));
}
__device__ __forceinline__ uint32_t smem_u32(const void* p) {
    uint32_t a;
    asm("{ .reg .u64 t; cvta.to.shared.u64 t, %1; cvt.u32.u64 %0, t; }" : "=r"(a) : "l"(p));
    return a;
}
__device__ __forceinline__ void cpasync16(uint32_t s, const void* g) {
    asm volatile("cp.async.cg.shared.global [%0], [%1], 16;" :: "r"(s), "l"(g));
}
__device__ __forceinline__ void cp_commit() { asm volatile("cp.async.commit_group;" ::: "memory"); }
__device__ __forceinline__ void cp_wait1()  { asm volatile("cp.async.wait_group 1;" ::: "memory"); }

__device__ __forceinline__ uint32_t h2pack(float a, float b) {
    __half2 h = __floats2half2_rn(a, b);
    return *(uint32_t*)&h;
}

// ---------------- pre-pass: f32 -> fp16 weight convert ----------------
__global__ void __launch_bounds__(256)
convert_w_kernel(const float* __restrict__ W, __half* __restrict__ Wh)
{
    long i = ((long)blockIdx.x * 256 + threadIdx.x) * 8;
    float4 v0 = *(const float4*)&W[i];
    float4 v1 = *(const float4*)&W[i + 4];
    uint4 o;
    o.x = h2pack(v0.x, v0.y); o.y = h2pack(v0.z, v0.w);
    o.z = h2pack(v1.x, v1.y); o.w = h2pack(v1.z, v1.w);
    *(uint4*)&Wh[i] = o;
}

// ---------------- pre-pass: transpose x [b][K][4096] -> Xt [b][n][K] fp16 ----------------
__global__ void __launch_bounds__(256)
transpose_x_kernel(const float* __restrict__ X, __half* __restrict__ Xt, int K)
{
    __shared__ float ts[64][65];
    int n0 = blockIdx.x * 64, k0 = blockIdx.y * 64, b = blockIdx.z;
    int tid = threadIdx.x;
    const float* Xb = X + (long)b * K * HW;
#pragma unroll
    for (int i = 0; i < 16; i++) {
        int idx = tid + i * 256;
        int k = idx >> 6, n = idx & 63;
        ts[k][n] = Xb[(long)(k0 + k) * HW + n0 + n];
    }
    __syncthreads();
    __half* Xo = Xt + (long)b * HW * K;
#pragma unroll
    for (int i = 0; i < 4; i++) {
        int c = tid + i * 256;
        int n = c >> 4, kc = (c & 15) * 4;
        uint2 o;
        o.x = h2pack(ts[kc + 0][n], ts[kc + 1][n]);
        o.y = h2pack(ts[kc + 2][n], ts[kc + 3][n]);
        *(uint2*)&Xo[(long)(n0 + n) * K + k0 + kc] = o;
    }
}

// ---------------- fp16 GEMM: warp tile 64x64, ldmatrix, BK=64, 3-stage cp.async ----------
// CTA 128x128, 4 warps (2m x 2n). Row = 64 halves (128B) padded to 144B:
// ldmatrix 8-row phases hit banks {4r..4r+3} -> exact 32-bank cover, conflict-free.
// Sync order per stage (proven R12): wait -> __syncthreads -> issue -> compute.
#define ROW_B 144
#define B_OFFS (128 * ROW_B)                      // 18432: B region start in stage
#define STAGE_BYTES (2 * 128 * ROW_B)             // 36864
#define NSTAGE 3
#define GSMEM_BYTES (NSTAGE * STAGE_BYTES)        // 110592

__global__ void __launch_bounds__(128, 2)
gemm_f16_kernel(const __half* __restrict__ Wh, const __half* __restrict__ Xt,
                float* __restrict__ Cm, const float* __restrict__ Addend,
                int M, int K)
{
    extern __shared__ char smem[];
    uint32_t sbase = smem_u32(smem);

    int b  = blockIdx.z;
    const __half* Xb = Xt + (long)b * HW * K;
    float*        Cb = Cm + (long)b * M * HW;
    const float*  Ab = Addend ? (Addend + (long)b * M * HW) : nullptr;

    int m0 = blockIdx.y * 128;
    int n0 = blockIdx.x * 128;

    int tid  = threadIdx.x;
    int lane = tid & 31, warp = tid >> 5;
    int wm = warp >> 1, wn = warp & 1;
    int g = lane >> 2, t4 = lane & 3;

    // cp.async mapping: one A row + one B row per thread, 8 x 16B chunks each
    const __half* gArow = Wh + (long)(m0 + tid) * K;
    const __half* gBrow = Xb + (long)(n0 + tid) * K;
    uint32_t oArow = tid * ROW_B;
    uint32_t oBrow = B_OFFS + tid * ROW_B;

    // ldmatrix per-warp base offsets within a stage
    uint32_t aOff = (wm * 64 + (lane & 15)) * ROW_B + (lane >> 4) * 16;
    uint32_t bOff = B_OFFS + (wn * 64 + ((lane >> 4) << 3) + (lane & 7)) * ROW_B
                  + ((lane >> 3) & 1) * 16;

    float acc[4][8][4];
#pragma unroll
    for (int i = 0; i < 4; i++)
#pragma unroll
        for (int j = 0; j < 8; j++)
#pragma unroll
            for (int q = 0; q < 4; q++) acc[i][j][q] = 0.f;

    int KT = K / 64;          // 8 (GEMM1) or 16 (GEMM2)

    // prologue: stages 0, 1
#pragma unroll
    for (int s = 0; s < NSTAGE - 1; s++) {
        long ko = (long)s * 64;
        uint32_t sq = sbase + s * STAGE_BYTES;
#pragma unroll
        for (int c = 0; c < 8; c++) {
            cpasync16(sq + oArow + c * 16, gArow + ko + c * 8);
            cpasync16(sq + oBrow + c * 16, gBrow + ko + c * 8);
        }
        cp_commit();
    }

    int buf = 0;
    for (int kt = 0; kt < KT; kt++) {
        cp_wait1();            // own stage-kt group done (<=1 younger outstanding)
        __syncthreads();       // ALL threads' stage-kt copies visible; prev reads done

        if (kt + NSTAGE - 1 < KT) {
            long ko = (long)(kt + NSTAGE - 1) * 64;
            int wbuf = kt + NSTAGE - 1;
            while (wbuf >= NSTAGE) wbuf -= NSTAGE;
            uint32_t sq = sbase + wbuf * STAGE_BYTES;
#pragma unroll
            for (int c = 0; c < 8; c++) {
                cpasync16(sq + oArow + c * 16, gArow + ko + c * 8);
                cpasync16(sq + oBrow + c * 16, gBrow + ko + c * 8);
            }
        }
        cp_commit();           // unconditional: group queue keeps advancing

        uint32_t sb = sbase + buf * STAGE_BYTES;
#pragma unroll
        for (int j = 0; j < 4; j++) {           // four k16 per BK=64 stage
            uint32_t aj = sb + aOff + j * 32;
            uint32_t bj = sb + bOff + j * 32;
            uint32_t af[4][4], bf[8][2];
#pragma unroll
            for (int mi = 0; mi < 4; mi++)
                ldmx4(af[mi][0], af[mi][1], af[mi][2], af[mi][3], aj + mi * (16 * ROW_B));
#pragma unroll
            for (int nj = 0; nj < 4; nj++)
                ldmx4(bf[2 * nj][0], bf[2 * nj][1], bf[2 * nj + 1][0], bf[2 * nj + 1][1],
                      bj + nj * (16 * ROW_B));
#pragma unroll
            for (int mi = 0; mi < 4; mi++)
#pragma unroll
                for (int nb = 0; nb < 8; nb++)
                    mma_f16(acc[mi][nb], af[mi], bf[nb]);
        }

        buf = (buf + 1 == NSTAGE) ? 0 : buf + 1;
    }

    // epilogue
#pragma unroll
    for (int mi = 0; mi < 4; mi++) {
#pragma unroll
        for (int nb = 0; nb < 8; nb++) {
            int row = m0 + wm * 64 + mi * 16 + g;
            int col = n0 + wn * 64 + nb * 8 + 2 * t4;
            float2 v0 = make_float2(acc[mi][nb][0], acc[mi][nb][1]);
            float2 v1 = make_float2(acc[mi][nb][2], acc[mi][nb][3]);
            long o0 = (long)row * HW + col;
            long o1 = (long)(row + 8) * HW + col;
            if (Ab) {
                float2 a0 = *(const float2*)&Ab[o0];
                float2 a1 = *(const float2*)&Ab[o1];
                v0.x += a0.x; v0.y += a0.y;
                v1.x += a1.x; v1.y += a1.y;
            }
            *(float2*)&Cb[o0] = v0;
            *(float2*)&Cb[o1] = v1;
        }
    }
}

// ---------------- fused depthwise 5x5 + grouped pointwise 8x8 ----------------
// Preload ALL 8 group channels' halo tiles into smem once, then register-strip compute.
__global__ void __launch_bounds__(256)
dwpw_kernel(const float* __restrict__ qkv, const float* __restrict__ w_dw,
            const float* __restrict__ w_pw, float* __restrict__ agg)
{
    __shared__ float in_s[8][36][36];     // 41472 B
    __shared__ float wpw_s[64];

    int tid = threadIdx.x;
    int tb  = blockIdx.x;
    int x0  = (tb & 1) * 32;
    int y0  = (tb >> 1) * 32;
    int grp = blockIdx.y;
    int b   = blockIdx.z;

    if (tid < 64) wpw_s[tid] = w_pw[(grp * 8 + (tid >> 3)) * 8 + (tid & 7)];

    const float* base = qkv + ((long)b * NCH3 + grp * 8) * HW;
    for (int idx = tid; idx < 8 * 36 * 36; idx += 256) {
        int c   = idx / 1296;
        int rem = idx - c * 1296;
        int r   = rem / 36, cc = rem - r * 36;
        int gy = y0 + r - 2, gx = x0 + cc - 2;
        float v = 0.f;
        if (gy >= 0 && gy < HH && gx >= 0 && gx < WW)
            v = base[(long)c * HW + gy * WW + gx];
        in_s[c][r][cc] = v;
    }
    __syncthreads();

    int py  = tid >> 3;
    int px0 = (tid & 7) << 2;

    float dacc[8][4];
#pragma unroll
    for (int c = 0; c < 8; c++) {
        int ch = grp * 8 + c;
        float wreg[25];
#pragma unroll
        for (int j = 0; j < 25; j++) wreg[j] = __ldg(&w_dw[ch * 25 + j]);

        float s0 = 0.f, s1 = 0.f, s2 = 0.f, s3 = 0.f;
#pragma unroll
        for (int dy = 0; dy < 5; dy++) {
            float4 u = *(const float4*)&in_s[c][py + dy][px0];
            float4 v = *(const float4*)&in_s[c][py + dy][px0 + 4];
            float a0 = u.x, a1 = u.y, a2 = u.z, a3 = u.w;
            float a4 = v.x, a5 = v.y, a6 = v.z, a7 = v.w;
            const float* w = wreg + dy * 5;
            s0 += a0 * w[0] + a1 * w[1] + a2 * w[2] + a3 * w[3] + a4 * w[4];
            s1 += a1 * w[0] + a2 * w[1] + a3 * w[2] + a4 * w[3] + a5 * w[4];
            s2 += a2 * w[0] + a3 * w[1] + a4 * w[2] + a5 * w[3] + a6 * w[4];
            s3 += a3 * w[0] + a4 * w[1] + a5 * w[2] + a6 * w[3] + a7 * w[4];
        }
        dacc[c][0] = s0; dacc[c][1] = s1; dacc[c][2] = s2; dacc[c][3] = s3;
    }

    long obase = ((long)b * NCH3 + grp * 8) * HW + (long)(y0 + py) * WW + (x0 + px0);
#pragma unroll
    for (int o = 0; o < 8; o++) {
        float t0 = 0.f, t1 = 0.f, t2 = 0.f, t3 = 0.f;
#pragma unroll
        for (int i = 0; i < 8; i++) {
            float w = wpw_s[o * 8 + i];
            t0 += w * dacc[i][0];
            t1 += w * dacc[i][1];
            t2 += w * dacc[i][2];
            t3 += w * dacc[i][3];
        }
        float4 r = make_float4(t0, t1, t2, t3);
        *(float4*)&agg[obase + (long)o * HW] = r;
    }
}

// ---------------- vk reduction ----------------
__global__ void __launch_bounds__(256)
vk_kernel(const float* __restrict__ qkv, const float* __restrict__ agg,
          float* __restrict__ vkout)
{
    int bh = blockIdx.x;
    int b = bh >> 7, h = bh & 127;
    const float* src = (h < 64)
        ? qkv + ((long)b * NCH3 + h * 24) * HW
        : agg + ((long)b * NCH3 + (h - 64) * 24) * HW;

    int tid = threadIdx.x, lane = tid & 31;
    float acc[72];
#pragma unroll
    for (int i = 0; i < 72; i++) acc[i] = 0.f;

    for (int n = tid; n < HW; n += 256) {
        float kv[8], vv[8];
#pragma unroll
        for (int e = 0; e < 8; e++) kv[e] = fmaxf(src[(long)(8 + e) * HW + n], 0.f);
#pragma unroll
        for (int d = 0; d < 8; d++) vv[d] = src[(long)(16 + d) * HW + n];
#pragma unroll
        for (int d = 0; d < 8; d++)
#pragma unroll
            for (int e = 0; e < 8; e++) acc[d * 8 + e] += vv[d] * kv[e];
#pragma unroll
        for (int e = 0; e < 8; e++) acc[64 + e] += kv[e];
    }
#pragma unroll
    for (int i = 0; i < 72; i++) {
#pragma unroll
        for (int off = 16; off > 0; off >>= 1)
            acc[i] += __shfl_xor_sync(0xFFFFFFFFu, acc[i], off);
    }
    __shared__ float red[72];
    if (tid < 72) red[tid] = 0.f;
    __syncthreads();
    if (lane == 0) {
#pragma unroll
        for (int i = 0; i < 72; i++) atomicAdd(&red[i], acc[i]);
    }
    __syncthreads();
    if (tid < 72) vkout[(long)bh * 72 + tid] = red[tid];
}

// ---------------- attention output + normalize -> fp16 [b][n][k], coalesced ----------------
#define ON_ROW 1032
__global__ void __launch_bounds__(256)
outnorm_kernel(const float* __restrict__ qkv, const float* __restrict__ agg,
               const float* __restrict__ vkin, __half* __restrict__ xt2)
{
    extern __shared__ float osm[];                 // vks[128*72] then buf
    float*  vks = osm;
    __half* buf = (__half*)(osm + NHEAD * 72);

    int b  = blockIdx.y;
    int n0 = blockIdx.x * 32;
    int tid = threadIdx.x, lane = tid & 31, warp = tid >> 5;

    for (int i = tid; i < NHEAD * 72; i += 256)
        vks[i] = vkin[((long)b * NHEAD) * 72 + i];
    __syncthreads();

    int n = n0 + lane;
#pragma unroll
    for (int it = 0; it < 16; it++) {
        int h = it * 8 + warp;
        const float* src = (h < 64)
            ? qkv + ((long)b * NCH3 + h * 24) * HW
            : agg + ((long)b * NCH3 + (h - 64) * 24) * HW;
        const float* vk = vks + h * 72;

        float q[8];
#pragma unroll
        for (int e = 0; e < 8; e++) q[e] = fmaxf(src[(long)e * HW + n], 0.f);

        float den = 0.f;
#pragma unroll
        for (int e = 0; e < 8; e++) den += vk[64 + e] * q[e];
        float inv = 1.f / (den + EPSF);

        float ov[8];
#pragma unroll
        for (int d = 0; d < 8; d++) {
            float num = 0.f;
#pragma unroll
            for (int e = 0; e < 8; e++) num += vk[d * 8 + e] * q[e];
            ov[d] = num * inv;
        }
        uint4 o;
        o.x = h2pack(ov[0], ov[1]);
        o.y = h2pack(ov[2], ov[3]);
        o.z = h2pack(ov[4], ov[5]);
        o.w = h2pack(ov[6], ov[7]);
        *(uint4*)&buf[lane * ON_ROW + h * 8] = o;
    }
    __syncthreads();

    for (int idx = tid; idx < 32 * 128; idx += 256) {
        int p = idx >> 7, c = idx & 127;
        uint4 v = *(const uint4*)&buf[p * ON_ROW + c * 8];
        *(uint4*)&xt2[((long)b * HW + n0 + p) * 1024 + c * 8] = v;
    }
}
#define ON_SMEM (NHEAD * 72 * 4 + 32 * ON_ROW * 2)   // 102912

// ---------------- launch ----------------
extern "C" void kernel_launch(void* const* d_in, const int* in_sizes, int n_in,
                              void* d_out, int out_size)
{
    const float* x      = (const float*)d_in[0];
    const float* w_qkv  = (const float*)d_in[1];
    const float* w_dw   = (const float*)d_in[2];
    const float* w_pw   = (const float*)d_in[3];
    const float* w_proj = (const float*)d_in[4];
    float* out = (float*)d_out;

    float *qkv_p, *agg_p, *vk_p;
    __half *xt1, *xt2, *wh1, *wh2;
    cudaGetSymbolAddress((void**)&qkv_p, g_qkv);
    cudaGetSymbolAddress((void**)&agg_p, g_agg);
    cudaGetSymbolAddress((void**)&vk_p,  g_vk);
    cudaGetSymbolAddress((void**)&xt1,   g_xt1);
    cudaGetSymbolAddress((void**)&xt2,   g_xt2);
    cudaGetSymbolAddress((void**)&wh1,   g_wh1);
    cudaGetSymbolAddress((void**)&wh2,   g_wh2);

    cudaFuncSetAttribute(gemm_f16_kernel,
                         cudaFuncAttributeMaxDynamicSharedMemorySize, GSMEM_BYTES);
    cudaFuncSetAttribute(outnorm_kernel,
                         cudaFuncAttributeMaxDynamicSharedMemorySize, ON_SMEM);

    // pre-passes
    convert_w_kernel<<<NCH3 * 512 / 2048, 256>>>(w_qkv, wh1);
    convert_w_kernel<<<512 * 1024 / 2048, 256>>>(w_proj, wh2);
    transpose_x_kernel<<<dim3(HW / 64, 512 / 64, B_SZ), 256>>>(x, xt1, 512);

    // 1) qkv = W_qkv @ x : M=1536, K=512
    gemm_f16_kernel<<<dim3(HW / 128, NCH3 / 128, B_SZ), 128, GSMEM_BYTES>>>(
        wh1, xt1, qkv_p, nullptr, NCH3, 512);

    // 2) agg = grouped_pw(depthwise5x5(qkv))
    dwpw_kernel<<<dim3(4, GROUPS, B_SZ), 256>>>(qkv_p, w_dw, w_pw, agg_p);

    // 3) vk reductions
    vk_kernel<<<B_SZ * NHEAD, 256>>>(qkv_p, agg_p, vk_p);

    // 4) attention normalize -> fp16 B operand for GEMM2 (coalesced)
    outnorm_kernel<<<dim3(HW / 32, B_SZ), 256, ON_SMEM>>>(qkv_p, agg_p, vk_p, xt2);

    // 5) out = x + W_proj @ outn : M=512, K=1024
    gemm_f16_kernel<<<dim3(HW / 128, 512 / 128, B_SZ), 128, GSMEM_BYTES>>>(
        wh2, xt2, out, x, 512, 1024);
}

// round 16
// speedup vs baseline: 1.2411x; 1.2411x over previous
#include <cuda_runtime.h>
#include <cuda_fp16.h>
#include <cstdint>

// Problem constants
#define B_SZ   4
#define C_IN   512
#define HW     4096
#define HH     64
#define WW     64
#define NCH3   1536
#define GROUPS 192
#define NHEAD  128
#define EPSF   1e-15f

// ---------------- scratch ----------------
__device__ float  g_qkv[(long)B_SZ * NCH3 * HW];
__device__ float  g_agg[(long)B_SZ * NCH3 * HW];
__device__ float  g_vk [B_SZ * NHEAD * 72];
__device__ __half g_xt1[(long)B_SZ * HW * 512];    // x transposed  [b][n][k]
__device__ __half g_xt2[(long)B_SZ * HW * 1024];   // outn          [b][n][k]
__device__ __half g_wh1[NCH3 * 512];               // w_qkv fp16
__device__ __half g_wh2[512 * 1024];               // w_proj fp16

// ---------------- helpers ----------------
__device__ __forceinline__ void mma_f16(float (&c)[4], const uint32_t (&a)[4], const uint32_t (&b)[2]) {
    asm volatile(
        "mma.sync.aligned.m16n8k16.row.col.f32.f16.f16.f32 "
        "{%0,%1,%2,%3}, {%4,%5,%6,%7}, {%8,%9}, {%0,%1,%2,%3};\n"
        : "+f"(c[0]), "+f"(c[1]), "+f"(c[2]), "+f"(c[3])
        : "r"(a[0]), "r"(a[1]), "r"(a[2]), "r"(a[3]), "r"(b[0]), "r"(b[1]));
}
__device__ __forceinline__ void ldmx4(uint32_t& r0, uint32_t& r1, uint32_t& r2, uint32_t& r3,
                                      uint32_t addr) {
    asm volatile("ldmatrix.sync.aligned.m8n8.x4.shared.b16 {%0,%1,%2,%3}, [%4];"
        : "=r"(r0), "=r"(r1), "=r"(r2), "=r"(r3) : "r"(addr));
}
__device__ __forceinline__ uint32_t smem_u32(const void* p) {
    uint32_t a;
    asm("{ .reg .u64 t; cvta.to.shared.u64 t, %1; cvt.u32.u64 %0, t; }" : "=r"(a) : "l"(p));
    return a;
}
__device__ __forceinline__ void cpasync16(uint32_t s, const void* g) {
    asm volatile("cp.async.cg.shared.global [%0], [%1], 16;" :: "r"(s), "l"(g));
}
__device__ __forceinline__ void cp_commit() { asm volatile("cp.async.commit_group;" ::: "memory"); }
__device__ __forceinline__ void cp_wait1()  { asm volatile("cp.async.wait_group 1;" ::: "memory"); }

__device__ __forceinline__ uint32_t h2pack(float a, float b) {
    __half2 h = __floats2half2_rn(a, b);
    return *(uint32_t*)&h;
}

// ---------------- pre-pass: f32 -> fp16 weight convert ----------------
__global__ void __launch_bounds__(256)
convert_w_kernel(const float* __restrict__ W, __half* __restrict__ Wh)
{
    long i = ((long)blockIdx.x * 256 + threadIdx.x) * 8;
    float4 v0 = *(const float4*)&W[i];
    float4 v1 = *(const float4*)&W[i + 4];
    uint4 o;
    o.x = h2pack(v0.x, v0.y); o.y = h2pack(v0.z, v0.w);
    o.z = h2pack(v1.x, v1.y); o.w = h2pack(v1.z, v1.w);
    *(uint4*)&Wh[i] = o;
}

// ---------------- pre-pass: transpose x [b][K][4096] -> Xt [b][n][K] fp16 ----------------
__global__ void __launch_bounds__(256)
transpose_x_kernel(const float* __restrict__ X, __half* __restrict__ Xt, int K)
{
    __shared__ float ts[64][65];
    int n0 = blockIdx.x * 64, k0 = blockIdx.y * 64, b = blockIdx.z;
    int tid = threadIdx.x;
    const float* Xb = X + (long)b * K * HW;
#pragma unroll
    for (int i = 0; i < 16; i++) {
        int idx = tid + i * 256;
        int k = idx >> 6, n = idx & 63;
        ts[k][n] = Xb[(long)(k0 + k) * HW + n0 + n];
    }
    __syncthreads();
    __half* Xo = Xt + (long)b * HW * K;
#pragma unroll
    for (int i = 0; i < 4; i++) {
        int c = tid + i * 256;
        int n = c >> 4, kc = (c & 15) * 4;
        uint2 o;
        o.x = h2pack(ts[kc + 0][n], ts[kc + 1][n]);
        o.y = h2pack(ts[kc + 2][n], ts[kc + 3][n]);
        *(uint2*)&Xo[(long)(n0 + n) * K + k0 + kc] = o;
    }
}

// ---------------- fp16 GEMM: warp tile 64x64, ldmatrix, BK=64, 3-stage, coalesced loads ----
// CTA 128x128, 4 warps (2m x 2n). Row = 64 halves (128B) padded to 144B.
// cp.async mapping: chunk idx = j*128 + tid -> row = idx>>3, seg = tid&7:
//   8 consecutive lanes fetch 128 CONTIGUOUS bytes of one row (R12-style coalescing).
// Sync order per stage (proven): wait -> __syncthreads -> issue -> compute.
#define ROW_B 144
#define B_OFFS (128 * ROW_B)                      // 18432: B region start in stage
#define STAGE_BYTES (2 * 128 * ROW_B)             // 36864
#define NSTAGE 3
#define GSMEM_BYTES (NSTAGE * STAGE_BYTES)        // 110592

__global__ void __launch_bounds__(128, 2)
gemm_f16_kernel(const __half* __restrict__ Wh, const __half* __restrict__ Xt,
                float* __restrict__ Cm, const float* __restrict__ Addend,
                int M, int K)
{
    extern __shared__ char smem[];
    uint32_t sbase = smem_u32(smem);

    int b  = blockIdx.z;
    const __half* Xb = Xt + (long)b * HW * K;
    float*        Cb = Cm + (long)b * M * HW;
    const float*  Ab = Addend ? (Addend + (long)b * M * HW) : nullptr;

    int m0 = blockIdx.y * 128;
    int n0 = blockIdx.x * 128;

    int tid  = threadIdx.x;
    int lane = tid & 31, warp = tid >> 5;
    int wm = warp >> 1, wn = warp & 1;
    int g = lane >> 2, t4 = lane & 3;

    // coalesced cp.async mapping: 8 A chunks + 8 B chunks per thread
    int rowbase = tid >> 3;          // 0..15
    int seg     = tid & 7;           // 0..7 (16B segment within 128B row payload)
    const __half* gA[8];
    const __half* gB[8];
    uint32_t oA[8], oB[8];
#pragma unroll
    for (int j = 0; j < 8; j++) {
        int row = j * 16 + rowbase;  // 0..127
        gA[j] = Wh + (long)(m0 + row) * K + seg * 8;
        gB[j] = Xb + (long)(n0 + row) * K + seg * 8;
        oA[j] = row * ROW_B + seg * 16;
        oB[j] = B_OFFS + row * ROW_B + seg * 16;
    }

    // ldmatrix per-warp base offsets within a stage (bank-verified for ROW_B=144)
    uint32_t aOff = (wm * 64 + (lane & 15)) * ROW_B + (lane >> 4) * 16;
    uint32_t bOff = B_OFFS + (wn * 64 + ((lane >> 4) << 3) + (lane & 7)) * ROW_B
                  + ((lane >> 3) & 1) * 16;

    float acc[4][8][4];
#pragma unroll
    for (int i = 0; i < 4; i++)
#pragma unroll
        for (int j = 0; j < 8; j++)
#pragma unroll
            for (int q = 0; q < 4; q++) acc[i][j][q] = 0.f;

    int KT = K / 64;          // 8 (GEMM1) or 16 (GEMM2)

    // prologue: stages 0, 1
#pragma unroll
    for (int s = 0; s < NSTAGE - 1; s++) {
        long ko = (long)s * 64;
        uint32_t sq = sbase + s * STAGE_BYTES;
#pragma unroll
        for (int j = 0; j < 8; j++) {
            cpasync16(sq + oA[j], gA[j] + ko);
            cpasync16(sq + oB[j], gB[j] + ko);
        }
        cp_commit();
    }

    int buf = 0;
    for (int kt = 0; kt < KT; kt++) {
        cp_wait1();            // own stage-kt group done (<=1 younger outstanding)
        __syncthreads();       // ALL threads' stage-kt copies visible; prev reads done

        if (kt + NSTAGE - 1 < KT) {
            long ko = (long)(kt + NSTAGE - 1) * 64;
            int wbuf = kt + NSTAGE - 1;
            while (wbuf >= NSTAGE) wbuf -= NSTAGE;
            uint32_t sq = sbase + wbuf * STAGE_BYTES;
#pragma unroll
            for (int j = 0; j < 8; j++) {
                cpasync16(sq + oA[j], gA[j] + ko);
                cpasync16(sq + oB[j], gB[j] + ko);
            }
        }
        cp_commit();           // unconditional: group queue keeps advancing

        uint32_t sb = sbase + buf * STAGE_BYTES;
#pragma unroll
        for (int j = 0; j < 4; j++) {           // four k16 per BK=64 stage
            uint32_t aj = sb + aOff + j * 32;
            uint32_t bj = sb + bOff + j * 32;
            uint32_t af[4][4], bf[8][2];
#pragma unroll
            for (int mi = 0; mi < 4; mi++)
                ldmx4(af[mi][0], af[mi][1], af[mi][2], af[mi][3], aj + mi * (16 * ROW_B));
#pragma unroll
            for (int nj = 0; nj < 4; nj++)
                ldmx4(bf[2 * nj][0], bf[2 * nj][1], bf[2 * nj + 1][0], bf[2 * nj + 1][1],
                      bj + nj * (16 * ROW_B));
#pragma unroll
            for (int mi = 0; mi < 4; mi++)
#pragma unroll
                for (int nb = 0; nb < 8; nb++)
                    mma_f16(acc[mi][nb], af[mi], bf[nb]);
        }

        buf = (buf + 1 == NSTAGE) ? 0 : buf + 1;
    }

    // epilogue
#pragma unroll
    for (int mi = 0; mi < 4; mi++) {
#pragma unroll
        for (int nb = 0; nb < 8; nb++) {
            int row = m0 + wm * 64 + mi * 16 + g;
            int col = n0 + wn * 64 + nb * 8 + 2 * t4;
            float2 v0 = make_float2(acc[mi][nb][0], acc[mi][nb][1]);
            float2 v1 = make_float2(acc[mi][nb][2], acc[mi][nb][3]);
            long o0 = (long)row * HW + col;
            long o1 = (long)(row + 8) * HW + col;
            if (Ab) {
                float2 a0 = *(const float2*)&Ab[o0];
                float2 a1 = *(const float2*)&Ab[o1];
                v0.x += a0.x; v0.y += a0.y;
                v1.x += a1.x; v1.y += a1.y;
            }
            *(float2*)&Cb[o0] = v0;
            *(float2*)&Cb[o1] = v1;
        }
    }
}

// ---------------- fused depthwise 5x5 + grouped pointwise 8x8 ----------------
// Preload ALL 8 group channels' halo tiles into smem once, then register-strip compute.
__global__ void __launch_bounds__(256)
dwpw_kernel(const float* __restrict__ qkv, const float* __restrict__ w_dw,
            const float* __restrict__ w_pw, float* __restrict__ agg)
{
    __shared__ float in_s[8][36][36];     // 41472 B
    __shared__ float wpw_s[64];

    int tid = threadIdx.x;
    int tb  = blockIdx.x;
    int x0  = (tb & 1) * 32;
    int y0  = (tb >> 1) * 32;
    int grp = blockIdx.y;
    int b   = blockIdx.z;

    if (tid < 64) wpw_s[tid] = w_pw[(grp * 8 + (tid >> 3)) * 8 + (tid & 7)];

    const float* base = qkv + ((long)b * NCH3 + grp * 8) * HW;
    for (int idx = tid; idx < 8 * 36 * 36; idx += 256) {
        int c   = idx / 1296;
        int rem = idx - c * 1296;
        int r   = rem / 36, cc = rem - r * 36;
        int gy = y0 + r - 2, gx = x0 + cc - 2;
        float v = 0.f;
        if (gy >= 0 && gy < HH && gx >= 0 && gx < WW)
            v = base[(long)c * HW + gy * WW + gx];
        in_s[c][r][cc] = v;
    }
    __syncthreads();

    int py  = tid >> 3;
    int px0 = (tid & 7) << 2;

    float dacc[8][4];
#pragma unroll
    for (int c = 0; c < 8; c++) {
        int ch = grp * 8 + c;
        float wreg[25];
#pragma unroll
        for (int j = 0; j < 25; j++) wreg[j] = __ldg(&w_dw[ch * 25 + j]);

        float s0 = 0.f, s1 = 0.f, s2 = 0.f, s3 = 0.f;
#pragma unroll
        for (int dy = 0; dy < 5; dy++) {
            float4 u = *(const float4*)&in_s[c][py + dy][px0];
            float4 v = *(const float4*)&in_s[c][py + dy][px0 + 4];
            float a0 = u.x, a1 = u.y, a2 = u.z, a3 = u.w;
            float a4 = v.x, a5 = v.y, a6 = v.z, a7 = v.w;
            const float* w = wreg + dy * 5;
            s0 += a0 * w[0] + a1 * w[1] + a2 * w[2] + a3 * w[3] + a4 * w[4];
            s1 += a1 * w[0] + a2 * w[1] + a3 * w[2] + a4 * w[3] + a5 * w[4];
            s2 += a2 * w[0] + a3 * w[1] + a4 * w[2] + a5 * w[3] + a6 * w[4];
            s3 += a3 * w[0] + a4 * w[1] + a5 * w[2] + a6 * w[3] + a7 * w[4];
        }
        dacc[c][0] = s0; dacc[c][1] = s1; dacc[c][2] = s2; dacc[c][3] = s3;
    }

    long obase = ((long)b * NCH3 + grp * 8) * HW + (long)(y0 + py) * WW + (x0 + px0);
#pragma unroll
    for (int o = 0; o < 8; o++) {
        float t0 = 0.f, t1 = 0.f, t2 = 0.f, t3 = 0.f;
#pragma unroll
        for (int i = 0; i < 8; i++) {
            float w = wpw_s[o * 8 + i];
            t0 += w * dacc[i][0];
            t1 += w * dacc[i][1];
            t2 += w * dacc[i][2];
            t3 += w * dacc[i][3];
        }
        float4 r = make_float4(t0, t1, t2, t3);
        *(float4*)&agg[obase + (long)o * HW] = r;
    }
}

// ---------------- vk reduction ----------------
__global__ void __launch_bounds__(256)
vk_kernel(const float* __restrict__ qkv, const float* __restrict__ agg,
          float* __restrict__ vkout)
{
    int bh = blockIdx.x;
    int b = bh >> 7, h = bh & 127;
    const float* src = (h < 64)
        ? qkv + ((long)b * NCH3 + h * 24) * HW
        : agg + ((long)b * NCH3 + (h - 64) * 24) * HW;

    int tid = threadIdx.x, lane = tid & 31;
    float acc[72];
#pragma unroll
    for (int i = 0; i < 72; i++) acc[i] = 0.f;

    for (int n = tid; n < HW; n += 256) {
        float kv[8], vv[8];
#pragma unroll
        for (int e = 0; e < 8; e++) kv[e] = fmaxf(src[(long)(8 + e) * HW + n], 0.f);
#pragma unroll
        for (int d = 0; d < 8; d++) vv[d] = src[(long)(16 + d) * HW + n];
#pragma unroll
        for (int d = 0; d < 8; d++)
#pragma unroll
            for (int e = 0; e < 8; e++) acc[d * 8 + e] += vv[d] * kv[e];
#pragma unroll
        for (int e = 0; e < 8; e++) acc[64 + e] += kv[e];
    }
#pragma unroll
    for (int i = 0; i < 72; i++) {
#pragma unroll
        for (int off = 16; off > 0; off >>= 1)
            acc[i] += __shfl_xor_sync(0xFFFFFFFFu, acc[i], off);
    }
    __shared__ float red[72];
    if (tid < 72) red[tid] = 0.f;
    __syncthreads();
    if (lane == 0) {
#pragma unroll
        for (int i = 0; i < 72; i++) atomicAdd(&red[i], acc[i]);
    }
    __syncthreads();
    if (tid < 72) vkout[(long)bh * 72 + tid] = red[tid];
}

// ---------------- attention output + normalize -> fp16 [b][n][k], coalesced ----------------
#define ON_ROW 1032
__global__ void __launch_bounds__(256)
outnorm_kernel(const float* __restrict__ qkv, const float* __restrict__ agg,
               const float* __restrict__ vkin, __half* __restrict__ xt2)
{
    extern __shared__ float osm[];                 // vks[128*72] then buf
    float*  vks = osm;
    __half* buf = (__half*)(osm + NHEAD * 72);

    int b  = blockIdx.y;
    int n0 = blockIdx.x * 32;
    int tid = threadIdx.x, lane = tid & 31, warp = tid >> 5;

    for (int i = tid; i < NHEAD * 72; i += 256)
        vks[i] = vkin[((long)b * NHEAD) * 72 + i];
    __syncthreads();

    int n = n0 + lane;
#pragma unroll
    for (int it = 0; it < 16; it++) {
        int h = it * 8 + warp;
        const float* src = (h < 64)
            ? qkv + ((long)b * NCH3 + h * 24) * HW
            : agg + ((long)b * NCH3 + (h - 64) * 24) * HW;
        const float* vk = vks + h * 72;

        float q[8];
#pragma unroll
        for (int e = 0; e < 8; e++) q[e] = fmaxf(src[(long)e * HW + n], 0.f);

        float den = 0.f;
#pragma unroll
        for (int e = 0; e < 8; e++) den += vk[64 + e] * q[e];
        float inv = 1.f / (den + EPSF);

        float ov[8];
#pragma unroll
        for (int d = 0; d < 8; d++) {
            float num = 0.f;
#pragma unroll
            for (int e = 0; e < 8; e++) num += vk[d * 8 + e] * q[e];
            ov[d] = num * inv;
        }
        uint4 o;
        o.x = h2pack(ov[0], ov[1]);
        o.y = h2pack(ov[2], ov[3]);
        o.z = h2pack(ov[4], ov[5]);
        o.w = h2pack(ov[6], ov[7]);
        *(uint4*)&buf[lane * ON_ROW + h * 8] = o;
    }
    __syncthreads();

    for (int idx = tid; idx < 32 * 128; idx += 256) {
        int p = idx >> 7, c = idx & 127;
        uint4 v = *(const uint4*)&buf[p * ON_ROW + c * 8];
        *(uint4*)&xt2[((long)b * HW + n0 + p) * 1024 + c * 8] = v;
    }
}
#define ON_SMEM (NHEAD * 72 * 4 + 32 * ON_ROW * 2)   // 102912

// ---------------- launch ----------------
extern "C" void kernel_launch(void* const* d_in, const int* in_sizes, int n_in,
                              void* d_out, int out_size)
{
    const float* x      = (const float*)d_in[0];
    const float* w_qkv  = (const float*)d_in[1];
    const float* w_dw   = (const float*)d_in[2];
    const float* w_pw   = (const float*)d_in[3];
    const float* w_proj = (const float*)d_in[4];
    float* out = (float*)d_out;

    float *qkv_p, *agg_p, *vk_p;
    __half *xt1, *xt2, *wh1, *wh2;
    cudaGetSymbolAddress((void**)&qkv_p, g_qkv);
    cudaGetSymbolAddress((void**)&agg_p, g_agg);
    cudaGetSymbolAddress((void**)&vk_p,  g_vk);
    cudaGetSymbolAddress((void**)&xt1,   g_xt1);
    cudaGetSymbolAddress((void**)&xt2,   g_xt2);
    cudaGetSymbolAddress((void**)&wh1,   g_wh1);
    cudaGetSymbolAddress((void**)&wh2,   g_wh2);

    cudaFuncSetAttribute(gemm_f16_kernel,
                         cudaFuncAttributeMaxDynamicSharedMemorySize, GSMEM_BYTES);
    cudaFuncSetAttribute(outnorm_kernel,
                         cudaFuncAttributeMaxDynamicSharedMemorySize, ON_SMEM);

    // pre-passes
    convert_w_kernel<<<NCH3 * 512 / 2048, 256>>>(w_qkv, wh1);
    convert_w_kernel<<<512 * 1024 / 2048, 256>>>(w_proj, wh2);
    transpose_x_kernel<<<dim3(HW / 64, 512 / 64, B_SZ), 256>>>(x, xt1, 512);

    // 1) qkv = W_qkv @ x : M=1536, K=512
    gemm_f16_kernel<<<dim3(HW / 128, NCH3 / 128, B_SZ), 128, GSMEM_BYTES>>>(
        wh1, xt1, qkv_p, nullptr, NCH3, 512);

    // 2) agg = grouped_pw(depthwise5x5(qkv))
    dwpw_kernel<<<dim3(4, GROUPS, B_SZ), 256>>>(qkv_p, w_dw, w_pw, agg_p);

    // 3) vk reductions
    vk_kernel<<<B_SZ * NHEAD, 256>>>(qkv_p, agg_p, vk_p);

    // 4) attention normalize -> fp16 B operand for GEMM2 (coalesced)
    outnorm_kernel<<<dim3(HW / 32, B_SZ), 256, ON_SMEM>>>(qkv_p, agg_p, vk_p, xt2);

    // 5) out = x + W_proj @ outn : M=512, K=1024
    gemm_f16_kernel<<<dim3(HW / 128, 512 / 128, B_SZ), 128, GSMEM_BYTES>>>(
        wh2, xt2, out, x, 512, 1024);
}

// round 17
// speedup vs baseline: 1.3363x; 1.0767x over previous
#include <cuda_runtime.h>
#include <cuda_fp16.h>
#include <cstdint>

// Problem constants
#define B_SZ   4
#define C_IN   512
#define HW     4096
#define HH     64
#define WW     64
#define NCH3   1536
#define GROUPS 192
#define NHEAD  128
#define EPSF   1e-15f

// ---------------- scratch ----------------
__device__ __half g_qkv[(long)B_SZ * NCH3 * HW];   // fp16 storage (R17)
__device__ __half g_agg[(long)B_SZ * NCH3 * HW];   // fp16 storage (R17)
__device__ float  g_vk [B_SZ * NHEAD * 72];
__device__ __half g_xt1[(long)B_SZ * HW * 512];    // x transposed  [b][n][k]
__device__ __half g_xt2[(long)B_SZ * HW * 1024];   // outn          [b][n][k]
__device__ __half g_wh1[NCH3 * 512];               // w_qkv fp16
__device__ __half g_wh2[512 * 1024];               // w_proj fp16

// ---------------- helpers ----------------
__device__ __forceinline__ void mma_f16(float (&c)[4], const uint32_t (&a)[4], const uint32_t (&b)[2]) {
    asm volatile(
        "mma.sync.aligned.m16n8k16.row.col.f32.f16.f16.f32 "
        "{%0,%1,%2,%3}, {%4,%5,%6,%7}, {%8,%9}, {%0,%1,%2,%3};\n"
        : "+f"(c[0]), "+f"(c[1]), "+f"(c[2]), "+f"(c[3])
        : "r"(a[0]), "r"(a[1]), "r"(a[2]), "r"(a[3]), "r"(b[0]), "r"(b[1]));
}
__device__ __forceinline__ void ldmx4(uint32_t& r0, uint32_t& r1, uint32_t& r2, uint32_t& r3,
                                      uint32_t addr) {
    asm volatile("ldmatrix.sync.aligned.m8n8.x4.shared.b16 {%0,%1,%2,%3}, [%4];"
        : "=r"(r0), "=r"(r1), "=r"(r2), "=r"(r3) : "r"(addr));
}
__device__ __forceinline__ uint32_t smem_u32(const void* p) {
    uint32_t a;
    asm("{ .reg .u64 t; cvta.to.shared.u64 t, %1; cvt.u32.u64 %0, t; }" : "=r"(a) : "l"(p));
    return a;
}
__device__ __forceinline__ void cpasync16(uint32_t s, const void* g) {
    asm volatile("cp.async.cg.shared.global [%0], [%1], 16;" :: "r"(s), "l"(g));
}
__device__ __forceinline__ void cp_commit() { asm volatile("cp.async.commit_group;" ::: "memory"); }
__device__ __forceinline__ void cp_wait1()  { asm volatile("cp.async.wait_group 1;" ::: "memory"); }

__device__ __forceinline__ uint32_t h2pack(float a, float b) {
    __half2 h = __floats2half2_rn(a, b);
    return *(uint32_t*)&h;
}

// ---------------- pre-pass: f32 -> fp16 weight convert ----------------
__global__ void __launch_bounds__(256)
convert_w_kernel(const float* __restrict__ W, __half* __restrict__ Wh)
{
    long i = ((long)blockIdx.x * 256 + threadIdx.x) * 8;
    float4 v0 = *(const float4*)&W[i];
    float4 v1 = *(const float4*)&W[i + 4];
    uint4 o;
    o.x = h2pack(v0.x, v0.y); o.y = h2pack(v0.z, v0.w);
    o.z = h2pack(v1.x, v1.y); o.w = h2pack(v1.z, v1.w);
    *(uint4*)&Wh[i] = o;
}

// ---------------- pre-pass: transpose x [b][K][4096] -> Xt [b][n][K] fp16 ----------------
__global__ void __launch_bounds__(256)
transpose_x_kernel(const float* __restrict__ X, __half* __restrict__ Xt, int K)
{
    __shared__ float ts[64][65];
    int n0 = blockIdx.x * 64, k0 = blockIdx.y * 64, b = blockIdx.z;
    int tid = threadIdx.x;
    const float* Xb = X + (long)b * K * HW;
#pragma unroll
    for (int i = 0; i < 16; i++) {
        int idx = tid + i * 256;
        int k = idx >> 6, n = idx & 63;
        ts[k][n] = Xb[(long)(k0 + k) * HW + n0 + n];
    }
    __syncthreads();
    __half* Xo = Xt + (long)b * HW * K;
#pragma unroll
    for (int i = 0; i < 4; i++) {
        int c = tid + i * 256;
        int n = c >> 4, kc = (c & 15) * 4;
        uint2 o;
        o.x = h2pack(ts[kc + 0][n], ts[kc + 1][n]);
        o.y = h2pack(ts[kc + 2][n], ts[kc + 3][n]);
        *(uint2*)&Xo[(long)(n0 + n) * K + k0 + kc] = o;
    }
}

// ---------------- fp16 GEMM: warp tile 64x64, ldmatrix, BK=64, 3-stage (R16 proven) ----
// HALF_OUT=true -> write fp16 C (qkv); false -> fp32 C + fp32 addend (residual).
#define ROW_B 144
#define B_OFFS (128 * ROW_B)                      // 18432
#define STAGE_BYTES (2 * 128 * ROW_B)             // 36864
#define NSTAGE 3
#define GSMEM_BYTES (NSTAGE * STAGE_BYTES)        // 110592

template<bool HALF_OUT>
__global__ void __launch_bounds__(128, 2)
gemm_f16_kernel(const __half* __restrict__ Wh, const __half* __restrict__ Xt,
                void* __restrict__ Cm, const float* __restrict__ Addend,
                int M, int K)
{
    extern __shared__ char smem[];
    uint32_t sbase = smem_u32(smem);

    int b  = blockIdx.z;
    const __half* Xb = Xt + (long)b * HW * K;
    const float*  Ab = Addend ? (Addend + (long)b * M * HW) : nullptr;

    int m0 = blockIdx.y * 128;
    int n0 = blockIdx.x * 128;

    int tid  = threadIdx.x;
    int lane = tid & 31, warp = tid >> 5;
    int wm = warp >> 1, wn = warp & 1;
    int g = lane >> 2, t4 = lane & 3;

    // coalesced cp.async mapping: 8 A chunks + 8 B chunks per thread
    int rowbase = tid >> 3;
    int seg     = tid & 7;
    const __half* gA[8];
    const __half* gB[8];
    uint32_t oA[8], oB[8];
#pragma unroll
    for (int j = 0; j < 8; j++) {
        int row = j * 16 + rowbase;
        gA[j] = Wh + (long)(m0 + row) * K + seg * 8;
        gB[j] = Xb + (long)(n0 + row) * K + seg * 8;
        oA[j] = row * ROW_B + seg * 16;
        oB[j] = B_OFFS + row * ROW_B + seg * 16;
    }

    uint32_t aOff = (wm * 64 + (lane & 15)) * ROW_B + (lane >> 4) * 16;
    uint32_t bOff = B_OFFS + (wn * 64 + ((lane >> 4) << 3) + (lane & 7)) * ROW_B
                  + ((lane >> 3) & 1) * 16;

    float acc[4][8][4];
#pragma unroll
    for (int i = 0; i < 4; i++)
#pragma unroll
        for (int j = 0; j < 8; j++)
#pragma unroll
            for (int q = 0; q < 4; q++) acc[i][j][q] = 0.f;

    int KT = K / 64;

    // prologue: stages 0, 1
#pragma unroll
    for (int s = 0; s < NSTAGE - 1; s++) {
        long ko = (long)s * 64;
        uint32_t sq = sbase + s * STAGE_BYTES;
#pragma unroll
        for (int j = 0; j < 8; j++) {
            cpasync16(sq + oA[j], gA[j] + ko);
            cpasync16(sq + oB[j], gB[j] + ko);
        }
        cp_commit();
    }

    int buf = 0;
    for (int kt = 0; kt < KT; kt++) {
        cp_wait1();
        __syncthreads();

        if (kt + NSTAGE - 1 < KT) {
            long ko = (long)(kt + NSTAGE - 1) * 64;
            int wbuf = kt + NSTAGE - 1;
            while (wbuf >= NSTAGE) wbuf -= NSTAGE;
            uint32_t sq = sbase + wbuf * STAGE_BYTES;
#pragma unroll
            for (int j = 0; j < 8; j++) {
                cpasync16(sq + oA[j], gA[j] + ko);
                cpasync16(sq + oB[j], gB[j] + ko);
            }
        }
        cp_commit();

        uint32_t sb = sbase + buf * STAGE_BYTES;
#pragma unroll
        for (int j = 0; j < 4; j++) {
            uint32_t aj = sb + aOff + j * 32;
            uint32_t bj = sb + bOff + j * 32;
            uint32_t af[4][4], bf[8][2];
#pragma unroll
            for (int mi = 0; mi < 4; mi++)
                ldmx4(af[mi][0], af[mi][1], af[mi][2], af[mi][3], aj + mi * (16 * ROW_B));
#pragma unroll
            for (int nj = 0; nj < 4; nj++)
                ldmx4(bf[2 * nj][0], bf[2 * nj][1], bf[2 * nj + 1][0], bf[2 * nj + 1][1],
                      bj + nj * (16 * ROW_B));
#pragma unroll
            for (int mi = 0; mi < 4; mi++)
#pragma unroll
                for (int nb = 0; nb < 8; nb++)
                    mma_f16(acc[mi][nb], af[mi], bf[nb]);
        }

        buf = (buf + 1 == NSTAGE) ? 0 : buf + 1;
    }

    // epilogue
#pragma unroll
    for (int mi = 0; mi < 4; mi++) {
#pragma unroll
        for (int nb = 0; nb < 8; nb++) {
            int row = m0 + wm * 64 + mi * 16 + g;
            int col = n0 + wn * 64 + nb * 8 + 2 * t4;
            long o0 = (long)row * HW + col;
            long o1 = (long)(row + 8) * HW + col;
            if (HALF_OUT) {
                __half* Cb = (__half*)Cm + (long)b * M * HW;
                *(uint32_t*)&Cb[o0] = h2pack(acc[mi][nb][0], acc[mi][nb][1]);
                *(uint32_t*)&Cb[o1] = h2pack(acc[mi][nb][2], acc[mi][nb][3]);
            } else {
                float* Cb = (float*)Cm + (long)b * M * HW;
                float2 v0 = make_float2(acc[mi][nb][0], acc[mi][nb][1]);
                float2 v1 = make_float2(acc[mi][nb][2], acc[mi][nb][3]);
                if (Ab) {
                    float2 a0 = *(const float2*)&Ab[o0];
                    float2 a1 = *(const float2*)&Ab[o1];
                    v0.x += a0.x; v0.y += a0.y;
                    v1.x += a1.x; v1.y += a1.y;
                }
                *(float2*)&Cb[o0] = v0;
                *(float2*)&Cb[o1] = v1;
            }
        }
    }
}

// ---------------- fused depthwise 5x5 + grouped pointwise 8x8 (fp16 I/O) ----------------
__global__ void __launch_bounds__(256)
dwpw_kernel(const __half* __restrict__ qkv, const float* __restrict__ w_dw,
            const float* __restrict__ w_pw, __half* __restrict__ agg)
{
    __shared__ float in_s[8][36][36];     // 41472 B
    __shared__ float wpw_s[64];

    int tid = threadIdx.x;
    int tb  = blockIdx.x;
    int x0  = (tb & 1) * 32;
    int y0  = (tb >> 1) * 32;
    int grp = blockIdx.y;
    int b   = blockIdx.z;

    if (tid < 64) wpw_s[tid] = w_pw[(grp * 8 + (tid >> 3)) * 8 + (tid & 7)];

    const __half* base = qkv + ((long)b * NCH3 + grp * 8) * HW;
    for (int idx = tid; idx < 8 * 36 * 36; idx += 256) {
        int c   = idx / 1296;
        int rem = idx - c * 1296;
        int r   = rem / 36, cc = rem - r * 36;
        int gy = y0 + r - 2, gx = x0 + cc - 2;
        float v = 0.f;
        if (gy >= 0 && gy < HH && gx >= 0 && gx < WW)
            v = __half2float(base[(long)c * HW + gy * WW + gx]);
        in_s[c][r][cc] = v;
    }
    __syncthreads();

    int py  = tid >> 3;
    int px0 = (tid & 7) << 2;

    float dacc[8][4];
#pragma unroll
    for (int c = 0; c < 8; c++) {
        int ch = grp * 8 + c;
        float wreg[25];
#pragma unroll
        for (int j = 0; j < 25; j++) wreg[j] = __ldg(&w_dw[ch * 25 + j]);

        float s0 = 0.f, s1 = 0.f, s2 = 0.f, s3 = 0.f;
#pragma unroll
        for (int dy = 0; dy < 5; dy++) {
            float4 u = *(const float4*)&in_s[c][py + dy][px0];
            float4 v = *(const float4*)&in_s[c][py + dy][px0 + 4];
            float a0 = u.x, a1 = u.y, a2 = u.z, a3 = u.w;
            float a4 = v.x, a5 = v.y, a6 = v.z, a7 = v.w;
            const float* w = wreg + dy * 5;
            s0 += a0 * w[0] + a1 * w[1] + a2 * w[2] + a3 * w[3] + a4 * w[4];
            s1 += a1 * w[0] + a2 * w[1] + a3 * w[2] + a4 * w[3] + a5 * w[4];
            s2 += a2 * w[0] + a3 * w[1] + a4 * w[2] + a5 * w[3] + a6 * w[4];
            s3 += a3 * w[0] + a4 * w[1] + a5 * w[2] + a6 * w[3] + a7 * w[4];
        }
        dacc[c][0] = s0; dacc[c][1] = s1; dacc[c][2] = s2; dacc[c][3] = s3;
    }

    long obase = ((long)b * NCH3 + grp * 8) * HW + (long)(y0 + py) * WW + (x0 + px0);
#pragma unroll
    for (int o = 0; o < 8; o++) {
        float t0 = 0.f, t1 = 0.f, t2 = 0.f, t3 = 0.f;
#pragma unroll
        for (int i = 0; i < 8; i++) {
            float w = wpw_s[o * 8 + i];
            t0 += w * dacc[i][0];
            t1 += w * dacc[i][1];
            t2 += w * dacc[i][2];
            t3 += w * dacc[i][3];
        }
        uint2 r;
        r.x = h2pack(t0, t1);
        r.y = h2pack(t2, t3);
        *(uint2*)&agg[obase + (long)o * HW] = r;
    }
}

// ---------------- vk reduction (fp16 input) ----------------
__global__ void __launch_bounds__(256)
vk_kernel(const __half* __restrict__ qkv, const __half* __restrict__ agg,
          float* __restrict__ vkout)
{
    int bh = blockIdx.x;
    int b = bh >> 7, h = bh & 127;
    const __half* src = (h < 64)
        ? qkv + ((long)b * NCH3 + h * 24) * HW
        : agg + ((long)b * NCH3 + (h - 64) * 24) * HW;

    int tid = threadIdx.x, lane = tid & 31;
    float acc[72];
#pragma unroll
    for (int i = 0; i < 72; i++) acc[i] = 0.f;

    for (int n = tid; n < HW; n += 256) {
        float kv[8], vv[8];
#pragma unroll
        for (int e = 0; e < 8; e++) kv[e] = fmaxf(__half2float(src[(long)(8 + e) * HW + n]), 0.f);
#pragma unroll
        for (int d = 0; d < 8; d++) vv[d] = __half2float(src[(long)(16 + d) * HW + n]);
#pragma unroll
        for (int d = 0; d < 8; d++)
#pragma unroll
            for (int e = 0; e < 8; e++) acc[d * 8 + e] += vv[d] * kv[e];
#pragma unroll
        for (int e = 0; e < 8; e++) acc[64 + e] += kv[e];
    }
#pragma unroll
    for (int i = 0; i < 72; i++) {
#pragma unroll
        for (int off = 16; off > 0; off >>= 1)
            acc[i] += __shfl_xor_sync(0xFFFFFFFFu, acc[i], off);
    }
    __shared__ float red[72];
    if (tid < 72) red[tid] = 0.f;
    __syncthreads();
    if (lane == 0) {
#pragma unroll
        for (int i = 0; i < 72; i++) atomicAdd(&red[i], acc[i]);
    }
    __syncthreads();
    if (tid < 72) vkout[(long)bh * 72 + tid] = red[tid];
}

// ---------------- attention output + normalize -> fp16 [b][n][k], coalesced ----------------
#define ON_ROW 1032
__global__ void __launch_bounds__(256)
outnorm_kernel(const __half* __restrict__ qkv, const __half* __restrict__ agg,
               const float* __restrict__ vkin, __half* __restrict__ xt2)
{
    extern __shared__ float osm[];                 // vks[128*72] then buf
    float*  vks = osm;
    __half* buf = (__half*)(osm + NHEAD * 72);

    int b  = blockIdx.y;
    int n0 = blockIdx.x * 32;
    int tid = threadIdx.x, lane = tid & 31, warp = tid >> 5;

    for (int i = tid; i < NHEAD * 72; i += 256)
        vks[i] = vkin[((long)b * NHEAD) * 72 + i];
    __syncthreads();

    int n = n0 + lane;
#pragma unroll
    for (int it = 0; it < 16; it++) {
        int h = it * 8 + warp;
        const __half* src = (h < 64)
            ? qkv + ((long)b * NCH3 + h * 24) * HW
            : agg + ((long)b * NCH3 + (h - 64) * 24) * HW;
        const float* vk = vks + h * 72;

        float q[8];
#pragma unroll
        for (int e = 0; e < 8; e++) q[e] = fmaxf(__half2float(src[(long)e * HW + n]), 0.f);

        float den = 0.f;
#pragma unroll
        for (int e = 0; e < 8; e++) den += vk[64 + e] * q[e];
        float inv = 1.f / (den + EPSF);

        float ov[8];
#pragma unroll
        for (int d = 0; d < 8; d++) {
            float num = 0.f;
#pragma unroll
            for (int e = 0; e < 8; e++) num += vk[d * 8 + e] * q[e];
            ov[d] = num * inv;
        }
        uint4 o;
        o.x = h2pack(ov[0], ov[1]);
        o.y = h2pack(ov[2], ov[3]);
        o.z = h2pack(ov[4], ov[5]);
        o.w = h2pack(ov[6], ov[7]);
        *(uint4*)&buf[lane * ON_ROW + h * 8] = o;
    }
    __syncthreads();

    for (int idx = tid; idx < 32 * 128; idx += 256) {
        int p = idx >> 7, c = idx & 127;
        uint4 v = *(const uint4*)&buf[p * ON_ROW + c * 8];
        *(uint4*)&xt2[((long)b * HW + n0 + p) * 1024 + c * 8] = v;
    }
}
#define ON_SMEM (NHEAD * 72 * 4 + 32 * ON_ROW * 2)   // 102912

// ---------------- launch ----------------
extern "C" void kernel_launch(void* const* d_in, const int* in_sizes, int n_in,
                              void* d_out, int out_size)
{
    const float* x      = (const float*)d_in[0];
    const float* w_qkv  = (const float*)d_in[1];
    const float* w_dw   = (const float*)d_in[2];
    const float* w_pw   = (const float*)d_in[3];
    const float* w_proj = (const float*)d_in[4];
    float* out = (float*)d_out;

    float *vk_p;
    __half *qkv_p, *agg_p, *xt1, *xt2, *wh1, *wh2;
    cudaGetSymbolAddress((void**)&qkv_p, g_qkv);
    cudaGetSymbolAddress((void**)&agg_p, g_agg);
    cudaGetSymbolAddress((void**)&vk_p,  g_vk);
    cudaGetSymbolAddress((void**)&xt1,   g_xt1);
    cudaGetSymbolAddress((void**)&xt2,   g_xt2);
    cudaGetSymbolAddress((void**)&wh1,   g_wh1);
    cudaGetSymbolAddress((void**)&wh2,   g_wh2);

    cudaFuncSetAttribute(gemm_f16_kernel<true>,
                         cudaFuncAttributeMaxDynamicSharedMemorySize, GSMEM_BYTES);
    cudaFuncSetAttribute(gemm_f16_kernel<false>,
                         cudaFuncAttributeMaxDynamicSharedMemorySize, GSMEM_BYTES);
    cudaFuncSetAttribute(outnorm_kernel,
                         cudaFuncAttributeMaxDynamicSharedMemorySize, ON_SMEM);

    // pre-passes
    convert_w_kernel<<<NCH3 * 512 / 2048, 256>>>(w_qkv, wh1);
    convert_w_kernel<<<512 * 1024 / 2048, 256>>>(w_proj, wh2);
    transpose_x_kernel<<<dim3(HW / 64, 512 / 64, B_SZ), 256>>>(x, xt1, 512);

    // 1) qkv = W_qkv @ x : M=1536, K=512  (fp16 output)
    gemm_f16_kernel<true><<<dim3(HW / 128, NCH3 / 128, B_SZ), 128, GSMEM_BYTES>>>(
        wh1, xt1, qkv_p, nullptr, NCH3, 512);

    // 2) agg = grouped_pw(depthwise5x5(qkv))  (fp16 in/out)
    dwpw_kernel<<<dim3(4, GROUPS, B_SZ), 256>>>(qkv_p, w_dw, w_pw, agg_p);

    // 3) vk reductions (fp16 in)
    vk_kernel<<<B_SZ * NHEAD, 256>>>(qkv_p, agg_p, vk_p);

    // 4) attention normalize -> fp16 B operand for GEMM2
    outnorm_kernel<<<dim3(HW / 32, B_SZ), 256, ON_SMEM>>>(qkv_p, agg_p, vk_p, xt2);

    // 5) out = x + W_proj @ outn : M=512, K=1024  (fp32 output + residual)
    gemm_f16_kernel<false><<<dim3(HW / 128, 512 / 128, B_SZ), 128, GSMEM_BYTES>>>(
        wh2, xt2, out, x, 512, 1024);
}